// round 4
// baseline (speedup 1.0000x reference)
#include <cuda_runtime.h>

#define NODES  8448
#define NB     10
#define ITERS  5
#define TPB    768
#define NPT    11            // 768 * 11 = 8448
#define NBATCH 1024
#define RPC    2             // batch rows per CTA (packed as float2)
#define NGROUPS (NBATCH / RPC)   // 512

// smem: DOUBLE-BUFFERED float2 tanh table: 2 * 8448 * 8 = 135168 B
#define SMEM_BYTES (2 * NODES * 8)

// Global scratch (static __device__ arrays; no allocation).
__device__ unsigned int g_pk[5][NODES];        // u16 neighbor ids, 2-per-u32, SoA over j
__device__ float2       g_wllr[NGROUPS][NODES];
__device__ float2       g_P[NGROUPS][NODES];   // vm_{t-1}

// ---------------------------------------------------------------------------
__global__ void prep_idx_kernel(const int* __restrict__ check_idx)
{
    int k = blockIdx.x * blockDim.x + threadIdx.x;
    if (k < NODES * 5) {
        int n = k / 5, j = k % 5;
        unsigned a = (unsigned)check_idx[n * NB + 2 * j];
        unsigned b = (unsigned)check_idx[n * NB + 2 * j + 1];
        g_pk[j][n] = (a & 0xFFFFu) | (b << 16);
    }
}

__device__ __forceinline__ float tclip(float v)
{
    // tanh(clip(0.5*v, -9.9, 9.9)) — accurate path (ILP-rich polynomial)
    return tanhf(fminf(9.9f, fmaxf(-9.9f, 0.5f * v)));
}

// ---------------------------------------------------------------------------
__global__ __launch_bounds__(TPB, 1)
void ldpc2_kernel(const float* __restrict__ input_llr,
                  const float* __restrict__ w_ch,
                  const float* __restrict__ w_res,   // (2, NODES)
                  float*       __restrict__ out)
{
    extern __shared__ float2 smem[];
    float2* stbuf[2] = { smem, smem + NODES };       // ping-pong tanh tables

    const int tid  = threadIdx.x;
    const int g    = blockIdx.x;
    const int row0 = g * RPC;
    const float* llr0 = input_llr + (size_t)row0 * NODES;

    float2 cur[NPT];   // current var_messages (2 batch rows)

    // Prologue: weighted LLR; publish t for iteration 0 into buffer 0.
    #pragma unroll
    for (int i = 0; i < NPT; i++) {
        const int n = tid + i * TPB;
        const float wc = w_ch[n];
        float2 wl;
        wl.x = llr0[n]         * wc;
        wl.y = llr0[NODES + n] * wc;
        g_wllr[g][n] = wl;
        cur[i] = wl;
        stbuf[0][n] = make_float2(tclip(wl.x), tclip(wl.y));
    }
    __syncthreads();

    for (int it = 0; it < ITERS; it++) {
        const float2* __restrict__ sc = stbuf[it & 1];        // gather source
        float2*       __restrict__ sn = stbuf[(it + 1) & 1];  // next-iter table

        // Fused phase: gather + product + 2*atanh + residual + update + tanh
        // (store goes to the OTHER buffer -> no intra-iteration race).
        #pragma unroll 2
        for (int i = 0; i < NPT; i++) {
            const int n = tid + i * TPB;

            // prefetch packed neighbor indices (L2-hot after first iter)
            unsigned pk0 = g_pk[0][n], pk1 = g_pk[1][n], pk2 = g_pk[2][n];
            unsigned pk3 = g_pk[3][n], pk4 = g_pk[4][n];

            float2 a0 = sc[pk0 & 0xFFFFu], b0 = sc[pk0 >> 16];
            float2 a1 = sc[pk1 & 0xFFFFu], b1 = sc[pk1 >> 16];
            float2 a2 = sc[pk2 & 0xFFFFu], b2 = sc[pk2 >> 16];
            float2 a3 = sc[pk3 & 0xFFFFu], b3 = sc[pk3 >> 16];
            float2 a4 = sc[pk4 & 0xFFFFu], b4 = sc[pk4 >> 16];

            // balanced product tree (short dependency chains)
            float px = ((a0.x * b0.x) * (a1.x * b1.x)) *
                       ((a2.x * b2.x) * (a3.x * b3.x)) * (a4.x * b4.x);
            float py = ((a0.y * b0.y) * (a1.y * b1.y)) *
                       ((a2.y * b2.y) * (a3.y * b3.y)) * (a4.y * b4.y);

            px = fminf(0.999999f, fmaxf(-0.999999f, px));
            py = fminf(0.999999f, fmaxf(-0.999999f, py));
            const float cmx = logf((1.0f + px) / (1.0f - px));  // 2*atanh
            const float cmy = logf((1.0f + py) / (1.0f - py));

            const float w0 = w_res[n];
            const float w1 = w_res[NODES + n];
            float2 pr = make_float2(0.f, 0.f);
            if (it > 0) pr = g_P[g][n];

            const float2 c = cur[i];
            g_P[g][n] = c;                         // becomes vm_{t-1} next iter
            const float2 wl = g_wllr[g][n];

            float2 nv;
            nv.x = wl.x + cmx + w0 * c.x + w1 * pr.x;
            nv.y = wl.y + cmy + w0 * c.y + w1 * pr.y;
            cur[i] = nv;

            // tanh for the NEXT iteration, stored into the other buffer
            // (skippable on last iter, but harmless and keeps the loop uniform)
            sn[n] = make_float2(tclip(nv.x), tclip(nv.y));
        }
        __syncthreads();   // one sync per iteration
    }

    // Epilogue: soft_bits = sigmoid(vm + input_llr)
    #pragma unroll
    for (int i = 0; i < NPT; i++) {
        const int n = tid + i * TPB;
        const float2 c = cur[i];
        float* o = out + (size_t)row0 * NODES;
        const float zx = c.x + llr0[n];
        const float zy = c.y + llr0[NODES + n];
        o[n]         = 1.0f / (1.0f + expf(-zx));
        o[NODES + n] = 1.0f / (1.0f + expf(-zy));
    }
}

// ---------------------------------------------------------------------------
extern "C" void kernel_launch(void* const* d_in, const int* in_sizes, int n_in,
                              void* d_out, int out_size)
{
    const float* input_llr = (const float*)d_in[0];
    const float* w_ch      = (const float*)d_in[1];
    const float* w_res     = (const float*)d_in[2];
    const int*   check_idx = (const int*)d_in[3];
    // d_in[4] (var_index_tensor) is unused by the reference computation.
    float* out = (float*)d_out;

    prep_idx_kernel<<<(NODES * 5 + 255) / 256, 256>>>(check_idx);

    cudaFuncSetAttribute(ldpc2_kernel,
                         cudaFuncAttributeMaxDynamicSharedMemorySize, SMEM_BYTES);
    ldpc2_kernel<<<NGROUPS, TPB, SMEM_BYTES>>>(input_llr, w_ch, w_res, out);
}

// round 5
// speedup vs baseline: 1.1317x; 1.1317x over previous
#include <cuda_runtime.h>

#define NODES  8448
#define NB     10
#define ITERS  5
#define TPB    1024
#define NPTMAX 9             // ceil(8448/1024); threads 0..255 do 9, rest do 8
#define NBATCH 1024
#define RPC    4             // batch rows per CTA (packed as float4)
#define NGROUPS (NBATCH / RPC)   // 256

#define SMEM_BYTES (NODES * 16)  // float4 tanh buffer = 135168 B

// Global scratch (static __device__ arrays; no allocation).
__device__ unsigned int g_pk[5][NODES];       // u16 neighbor ids, 2-per-u32, SoA over j
__device__ float4       g_wllr[NGROUPS][NODES];
__device__ float4       g_P[NGROUPS][NODES];  // vm_{t-1}

// ---------------------------------------------------------------------------
__global__ void prep_idx_kernel(const int* __restrict__ check_idx)
{
    int k = blockIdx.x * blockDim.x + threadIdx.x;
    if (k < NODES * 5) {
        int n = k / 5, j = k % 5;
        unsigned a = (unsigned)check_idx[n * NB + 2 * j];
        unsigned b = (unsigned)check_idx[n * NB + 2 * j + 1];
        g_pk[j][n] = (a & 0xFFFFu) | (b << 16);
    }
}

// ---------------------------------------------------------------------------
__global__ __launch_bounds__(TPB, 1)
void ldpc4_kernel(const float* __restrict__ input_llr,
                  const float* __restrict__ w_ch,
                  const float* __restrict__ w_res,   // (2, NODES)
                  float*       __restrict__ out)
{
    extern __shared__ float4 st[];                   // tanh values, 4 rows packed
    const int tid  = threadIdx.x;
    const int g    = blockIdx.x;
    const int row0 = g * RPC;
    const float* llr0 = input_llr + (size_t)row0 * NODES;

    float4 cur[NPTMAX];   // current var_messages for this thread's nodes (4 rows)

    // Prologue: weighted LLR -> registers + global scratch (reloaded each iter).
    #pragma unroll
    for (int i = 0; i < NPTMAX; i++) {
        const int n = tid + i * TPB;
        if (n < NODES) {
            const float wc = w_ch[n];
            float4 wl;
            wl.x = llr0[n]             * wc;
            wl.y = llr0[NODES + n]     * wc;
            wl.z = llr0[2 * NODES + n] * wc;
            wl.w = llr0[3 * NODES + n] * wc;
            g_wllr[g][n] = wl;
            cur[i] = wl;
        }
    }

    for (int it = 0; it < ITERS; it++) {
        // Phase A: publish t = tanh(clip(0.5 * vm)) for all 4 rows (one LDS.128).
        #pragma unroll
        for (int i = 0; i < NPTMAX; i++) {
            const int n = tid + i * TPB;
            if (n < NODES) {
                const float4 v = cur[i];
                float4 t;
                t.x = tanhf(fminf(9.9f, fmaxf(-9.9f, 0.5f * v.x)));
                t.y = tanhf(fminf(9.9f, fmaxf(-9.9f, 0.5f * v.y)));
                t.z = tanhf(fminf(9.9f, fmaxf(-9.9f, 0.5f * v.z)));
                t.w = tanhf(fminf(9.9f, fmaxf(-9.9f, 0.5f * v.w)));
                st[n] = t;
            }
        }
        __syncthreads();

        // Phase B: gather 10 neighbors (one LDS.128 serves 4 rows), product,
        // 2*atanh, residual, update.
        #pragma unroll 2
        for (int i = 0; i < NPTMAX; i++) {
            const int n = tid + i * TPB;
            if (n < NODES) {
                const unsigned pk0 = g_pk[0][n], pk1 = g_pk[1][n];
                const unsigned pk2 = g_pk[2][n], pk3 = g_pk[3][n];
                const unsigned pk4 = g_pk[4][n];

                float4 p0 = st[pk0 & 0xFFFFu];
                float4 p1 = st[pk0 >> 16];
                {
                    const float4 a = st[pk1 & 0xFFFFu];
                    const float4 b = st[pk1 >> 16];
                    p0.x *= a.x; p0.y *= a.y; p0.z *= a.z; p0.w *= a.w;
                    p1.x *= b.x; p1.y *= b.y; p1.z *= b.z; p1.w *= b.w;
                }
                {
                    const float4 a = st[pk2 & 0xFFFFu];
                    const float4 b = st[pk2 >> 16];
                    p0.x *= a.x; p0.y *= a.y; p0.z *= a.z; p0.w *= a.w;
                    p1.x *= b.x; p1.y *= b.y; p1.z *= b.z; p1.w *= b.w;
                }
                {
                    const float4 a = st[pk3 & 0xFFFFu];
                    const float4 b = st[pk3 >> 16];
                    p0.x *= a.x; p0.y *= a.y; p0.z *= a.z; p0.w *= a.w;
                    p1.x *= b.x; p1.y *= b.y; p1.z *= b.z; p1.w *= b.w;
                }
                {
                    const float4 a = st[pk4 & 0xFFFFu];
                    const float4 b = st[pk4 >> 16];
                    p0.x *= a.x; p0.y *= a.y; p0.z *= a.z; p0.w *= a.w;
                    p1.x *= b.x; p1.y *= b.y; p1.z *= b.z; p1.w *= b.w;
                }
                float4 p;
                p.x = p0.x * p1.x;  p.y = p0.y * p1.y;
                p.z = p0.z * p1.z;  p.w = p0.w * p1.w;

                p.x = fminf(0.999999f, fmaxf(-0.999999f, p.x));
                p.y = fminf(0.999999f, fmaxf(-0.999999f, p.y));
                p.z = fminf(0.999999f, fmaxf(-0.999999f, p.z));
                p.w = fminf(0.999999f, fmaxf(-0.999999f, p.w));
                float4 cm;
                cm.x = logf((1.0f + p.x) / (1.0f - p.x));   // 2*atanh(p)
                cm.y = logf((1.0f + p.y) / (1.0f - p.y));
                cm.z = logf((1.0f + p.z) / (1.0f - p.z));
                cm.w = logf((1.0f + p.w) / (1.0f - p.w));

                const float w0 = w_res[n];
                const float w1 = w_res[NODES + n];
                float4 pr = make_float4(0.f, 0.f, 0.f, 0.f);
                if (it > 0) pr = g_P[g][n];

                const float4 c = cur[i];
                if (it < ITERS - 1) g_P[g][n] = c;     // dead on last iteration

                const float4 wl = g_wllr[g][n];
                float4 nv;
                nv.x = wl.x + cm.x + w0 * c.x + w1 * pr.x;
                nv.y = wl.y + cm.y + w0 * c.y + w1 * pr.y;
                nv.z = wl.z + cm.z + w0 * c.z + w1 * pr.z;
                nv.w = wl.w + cm.w + w0 * c.w + w1 * pr.w;
                cur[i] = nv;
            }
        }
        __syncthreads();   // protect st before next iteration's Phase A
    }

    // Epilogue: soft_bits = sigmoid(vm + input_llr), 4 coalesced row streams.
    #pragma unroll
    for (int i = 0; i < NPTMAX; i++) {
        const int n = tid + i * TPB;
        if (n < NODES) {
            const float4 c = cur[i];
            float* o = out + (size_t)row0 * NODES;
            const float zx = c.x + llr0[n];
            const float zy = c.y + llr0[NODES + n];
            const float zz = c.z + llr0[2 * NODES + n];
            const float zw = c.w + llr0[3 * NODES + n];
            o[n]             = 1.0f / (1.0f + expf(-zx));
            o[NODES + n]     = 1.0f / (1.0f + expf(-zy));
            o[2 * NODES + n] = 1.0f / (1.0f + expf(-zz));
            o[3 * NODES + n] = 1.0f / (1.0f + expf(-zw));
        }
    }
}

// ---------------------------------------------------------------------------
extern "C" void kernel_launch(void* const* d_in, const int* in_sizes, int n_in,
                              void* d_out, int out_size)
{
    const float* input_llr = (const float*)d_in[0];
    const float* w_ch      = (const float*)d_in[1];
    const float* w_res     = (const float*)d_in[2];
    const int*   check_idx = (const int*)d_in[3];
    // d_in[4] (var_index_tensor) is unused by the reference computation.
    float* out = (float*)d_out;

    prep_idx_kernel<<<(NODES * 5 + 255) / 256, 256>>>(check_idx);

    cudaFuncSetAttribute(ldpc4_kernel,
                         cudaFuncAttributeMaxDynamicSharedMemorySize, SMEM_BYTES);
    ldpc4_kernel<<<NGROUPS, TPB, SMEM_BYTES>>>(input_llr, w_ch, w_res, out);
}

// round 7
// speedup vs baseline: 1.1821x; 1.0446x over previous
#include <cuda_runtime.h>

#define NODES  8448
#define NB     10
#define ITERS  5
#define TPB    1024
#define NPTMAX 9             // ceil(8448/1024); threads 0..255 do 9, rest do 8
#define NBATCH 1024
#define RPC    4             // batch rows per CTA (packed as float4)
#define NGROUPS (NBATCH / RPC)   // 256
#define NQG    (NODES / 8)   // 1056 quarter-warp node groups

#define SMEM_BYTES (NODES * 16)  // float4 tanh table = 135168 B

// Global scratch (static __device__ arrays; no allocation).
__device__ unsigned int g_pk[5][NODES];       // u16 neighbor ids, 2-per-u32, slot-SoA
__device__ float4       g_wllr[NGROUPS][NODES];
__device__ float4       g_P[NGROUPS][NODES];  // vm_{t-1}

// ---------------------------------------------------------------------------
// Prep: for each aligned group of 8 nodes (one LDS quarter-warp phase), permute
// each node's 10 neighbor indices among the 10 gather slots so that, per slot,
// the 8 lanes' bank-groups (idx % 8) are as distinct as possible.
// The check-product is commutative, so any per-node permutation is exact.
__global__ void prep_sched_kernel(const int* __restrict__ check_idx)
{
    int grp = blockIdx.x * blockDim.x + threadIdx.x;
    if (grp >= NQG) return;

    int cnt[10][8];                       // per-slot bank-group occupancy
    #pragma unroll
    for (int s = 0; s < 10; s++)
        #pragma unroll
        for (int b = 0; b < 8; b++) cnt[s][b] = 0;

    unsigned perm[10];

    for (int ln = 0; ln < 8; ln++) {
        const int n = grp * 8 + ln;
        unsigned idxv[10];
        #pragma unroll
        for (int j = 0; j < 10; j++)
            idxv[j] = (unsigned)check_idx[n * NB + j];

        unsigned used = 0;                // bitmask of assigned slots
        #pragma unroll
        for (int j = 0; j < 10; j++) {
            const unsigned v  = idxv[j];
            const int      bg = (int)(v & 7u);
            int best = -1, bestc = 1 << 30;
            #pragma unroll
            for (int s = 0; s < 10; s++) {
                if (!(used & (1u << s)) && cnt[s][bg] < bestc) {
                    bestc = cnt[s][bg];
                    best  = s;
                }
            }
            used |= 1u << best;
            cnt[best][bg]++;
            perm[best] = v;
        }
        // pack slot pairs (2j, 2j+1) into u32, slot-SoA layout
        #pragma unroll
        for (int j = 0; j < 5; j++)
            g_pk[j][n] = (perm[2 * j] & 0xFFFFu) | (perm[2 * j + 1] << 16);
    }
}

// ---------------------------------------------------------------------------
__global__ __launch_bounds__(TPB, 1)
void ldpc4_kernel(const float* __restrict__ input_llr,
                  const float* __restrict__ w_ch,
                  const float* __restrict__ w_res,   // (2, NODES)
                  float*       __restrict__ out)
{
    extern __shared__ float4 st[];                   // tanh values, 4 rows packed
    const int tid  = threadIdx.x;
    const int g    = blockIdx.x;
    const int row0 = g * RPC;
    const float* llr0 = input_llr + (size_t)row0 * NODES;

    float4 cur[NPTMAX];   // current var_messages for this thread's nodes (4 rows)

    // Prologue: weighted LLR -> registers + global scratch.
    #pragma unroll
    for (int i = 0; i < NPTMAX; i++) {
        const int n = tid + i * TPB;
        if (n < NODES) {
            const float wc = w_ch[n];
            float4 wl;
            wl.x = llr0[n]             * wc;
            wl.y = llr0[NODES + n]     * wc;
            wl.z = llr0[2 * NODES + n] * wc;
            wl.w = llr0[3 * NODES + n] * wc;
            g_wllr[g][n] = wl;
            cur[i] = wl;
        }
    }

    for (int it = 0; it < ITERS; it++) {
        // Phase A: publish t = tanh(clip(0.5 * vm)) for all 4 rows (one STS.128).
        #pragma unroll
        for (int i = 0; i < NPTMAX; i++) {
            const int n = tid + i * TPB;
            if (n < NODES) {
                const float4 v = cur[i];
                float4 t;
                t.x = tanhf(fminf(9.9f, fmaxf(-9.9f, 0.5f * v.x)));
                t.y = tanhf(fminf(9.9f, fmaxf(-9.9f, 0.5f * v.y)));
                t.z = tanhf(fminf(9.9f, fmaxf(-9.9f, 0.5f * v.z)));
                t.w = tanhf(fminf(9.9f, fmaxf(-9.9f, 0.5f * v.w)));
                st[n] = t;
            }
        }
        __syncthreads();

        // Phase B: gather 10 scheduled neighbors (LDS.128 serves 4 rows),
        // product, 2*atanh, residual, update.
        #pragma unroll 2
        for (int i = 0; i < NPTMAX; i++) {
            const int n = tid + i * TPB;
            if (n < NODES) {
                const unsigned pk0 = g_pk[0][n], pk1 = g_pk[1][n];
                const unsigned pk2 = g_pk[2][n], pk3 = g_pk[3][n];
                const unsigned pk4 = g_pk[4][n];

                // prefetch iteration-state (L2 latency overlaps LDS work)
                float4 pr = make_float4(0.f, 0.f, 0.f, 0.f);
                if (it > 0) pr = g_P[g][n];
                const float4 wl = g_wllr[g][n];
                const float  w0 = w_res[n];
                const float  w1 = w_res[NODES + n];

                float4 p0 = st[pk0 & 0xFFFFu];
                float4 p1 = st[pk0 >> 16];
                {
                    const float4 a = st[pk1 & 0xFFFFu];
                    const float4 b = st[pk1 >> 16];
                    p0.x *= a.x; p0.y *= a.y; p0.z *= a.z; p0.w *= a.w;
                    p1.x *= b.x; p1.y *= b.y; p1.z *= b.z; p1.w *= b.w;
                }
                {
                    const float4 a = st[pk2 & 0xFFFFu];
                    const float4 b = st[pk2 >> 16];
                    p0.x *= a.x; p0.y *= a.y; p0.z *= a.z; p0.w *= a.w;
                    p1.x *= b.x; p1.y *= b.y; p1.z *= b.z; p1.w *= b.w;
                }
                {
                    const float4 a = st[pk3 & 0xFFFFu];
                    const float4 b = st[pk3 >> 16];
                    p0.x *= a.x; p0.y *= a.y; p0.z *= a.z; p0.w *= a.w;
                    p1.x *= b.x; p1.y *= b.y; p1.z *= b.z; p1.w *= b.w;
                }
                {
                    const float4 a = st[pk4 & 0xFFFFu];
                    const float4 b = st[pk4 >> 16];
                    p0.x *= a.x; p0.y *= a.y; p0.z *= a.z; p0.w *= a.w;
                    p1.x *= b.x; p1.y *= b.y; p1.z *= b.z; p1.w *= b.w;
                }
                float4 p;
                p.x = p0.x * p1.x;  p.y = p0.y * p1.y;
                p.z = p0.z * p1.z;  p.w = p0.w * p1.w;

                p.x = fminf(0.999999f, fmaxf(-0.999999f, p.x));
                p.y = fminf(0.999999f, fmaxf(-0.999999f, p.y));
                p.z = fminf(0.999999f, fmaxf(-0.999999f, p.z));
                p.w = fminf(0.999999f, fmaxf(-0.999999f, p.w));
                float4 cm;
                cm.x = logf((1.0f + p.x) / (1.0f - p.x));   // 2*atanh(p)
                cm.y = logf((1.0f + p.y) / (1.0f - p.y));
                cm.z = logf((1.0f + p.z) / (1.0f - p.z));
                cm.w = logf((1.0f + p.w) / (1.0f - p.w));

                const float4 c = cur[i];
                if (it < ITERS - 1) g_P[g][n] = c;     // dead on last iteration

                float4 nv;
                nv.x = wl.x + cm.x + w0 * c.x + w1 * pr.x;
                nv.y = wl.y + cm.y + w0 * c.y + w1 * pr.y;
                nv.z = wl.z + cm.z + w0 * c.z + w1 * pr.z;
                nv.w = wl.w + cm.w + w0 * c.w + w1 * pr.w;
                cur[i] = nv;
            }
        }
        __syncthreads();   // protect st before next iteration's Phase A
    }

    // Epilogue: soft_bits = sigmoid(vm + input_llr), 4 coalesced row streams.
    #pragma unroll
    for (int i = 0; i < NPTMAX; i++) {
        const int n = tid + i * TPB;
        if (n < NODES) {
            const float4 c = cur[i];
            float* o = out + (size_t)row0 * NODES;
            const float zx = c.x + llr0[n];
            const float zy = c.y + llr0[NODES + n];
            const float zz = c.z + llr0[2 * NODES + n];
            const float zw = c.w + llr0[3 * NODES + n];
            o[n]             = 1.0f / (1.0f + expf(-zx));
            o[NODES + n]     = 1.0f / (1.0f + expf(-zy));
            o[2 * NODES + n] = 1.0f / (1.0f + expf(-zz));
            o[3 * NODES + n] = 1.0f / (1.0f + expf(-zw));
        }
    }
}

// ---------------------------------------------------------------------------
extern "C" void kernel_launch(void* const* d_in, const int* in_sizes, int n_in,
                              void* d_out, int out_size)
{
    const float* input_llr = (const float*)d_in[0];
    const float* w_ch      = (const float*)d_in[1];
    const float* w_res     = (const float*)d_in[2];
    const int*   check_idx = (const int*)d_in[3];
    // d_in[4] (var_index_tensor) is unused by the reference computation.
    float* out = (float*)d_out;

    prep_sched_kernel<<<(NQG + 127) / 128, 128>>>(check_idx);

    cudaFuncSetAttribute(ldpc4_kernel,
                         cudaFuncAttributeMaxDynamicSharedMemorySize, SMEM_BYTES);
    ldpc4_kernel<<<NGROUPS, TPB, SMEM_BYTES>>>(input_llr, w_ch, w_res, out);
}